// round 13
// baseline (speedup 1.0000x reference)
#include <cuda_runtime.h>
#include <math.h>

#define B_  64
#define LQ  32
#define O_  128
#define LK  256
#define D_  128
#define FULLM 0xffffffffu
#define GRID_N 888          // 6 blocks/SM * 148 SMs

__device__ float g_acc[B_ * O_];   // i-half partial sums (zero-init, self-reset)
__device__ int   g_cnt[B_ * O_];

__device__ __forceinline__ bool mask_at(const void* buf, int idx, int mode) {
    if (mode == 0) return ((const int*)buf)[idx] != 0;
    if (mode == 2) return ((const float*)buf)[idx] != 0.0f;
    return ((const unsigned char*)buf)[idx] != 0;
}

__device__ __forceinline__ unsigned long long pk2(float a, float b) {
    unsigned long long r;
    asm("mov.b64 %0,{%1,%2};" : "=l"(r) : "f"(a), "f"(b));
    return r;
}
__device__ __forceinline__ void fma2(unsigned long long& d,
                                     unsigned long long a, unsigned long long b) {
    asm("fma.rn.f32x2 %0,%1,%2,%0;" : "+l"(d) : "l"(a), "l"(b));
}
__device__ __forceinline__ float2 upk2(unsigned long long v) {
    float2 r;
    asm("mov.b64 {%0,%1},%2;" : "=f"(r.x), "=f"(r.y) : "l"(v));
    return r;
}

// ---------------------------------------------------------------------------
// Grid 888 x 128 threads. Item = (active b, o, ihalf): 16i x 256j x 128d.
// Warp w (0..3): i rows = w*4 .. +4. Lane l: j in {4l..4l+3, 128+4l..+3}.
// acc[4][4] f32x2 (j-packed) = 32 regs. kt chunk = 16 d (16KB), 8 chunks.
// q pre-duplicated (16 rows, 16KB). Occupancy 6 -> 6 warps/SMSP.
// i-half partials combined via g_acc/g_cnt (order-independent; self-reset).
// ---------------------------------------------------------------------------
__global__ __launch_bounds__(128, 6)
void fused_score_kernel(const float* __restrict__ q,
                        const float* __restrict__ k,
                        const void* __restrict__ q_mask,
                        const void* __restrict__ k_mask,
                        const float* __restrict__ logit_scale,
                        float* __restrict__ out) {
    const int tid = threadIdx.x;
    const int w   = tid >> 5, l = tid & 31;

    __shared__ int s_nact;
    __shared__ unsigned char s_blist[B_];
    __shared__ unsigned char s_act[B_];
    extern __shared__ float smem[];
    unsigned long long* q2 = (unsigned long long*)smem;  // 2048 u64 = 16KB
    float* kt  = smem + 4096;       // 16*256 = 4096 f (swizzled [d][j] chunk)
    float* ivk = kt + 16 * LK;      // 256
    float* wm  = ivk + LK;          // 256
    float* ivq = wm + LK;           // 16
    float* red = ivq + 16;          // 16

    // ---- Phase A: dtype sniff + active flags + compact list ----
    int mode;
    {
        unsigned word = ((const unsigned*)q_mask)[l];   // first 128B safe all dtypes
        unsigned bi = __ballot_sync(FULLM, word <= 1u);
        unsigned bf = __ballot_sync(FULLM, word == 0u || word == 0x3F800000u);
        mode = (bi == FULLM) ? 0 : (bf == FULLM) ? 2 : 1;
    }
    {
        int bb = tid >> 1, sub = tid & 1;     // 64 b x 2 halves of 16 tokens
        int any = 0;
        #pragma unroll
        for (int e = 0; e < 16; e++)
            any |= mask_at(q_mask, bb * LQ + sub * 16 + e, mode) ? 1 : 0;
        any |= __shfl_xor_sync(FULLM, any, 1);
        if ((l & 1) == 0) s_act[bb] = (any == 0);
    }
    __syncthreads();
    if (w == 0) {
        unsigned f0 = __ballot_sync(FULLM, s_act[l] != 0);
        unsigned f1 = __ballot_sync(FULLM, s_act[32 + l] != 0);
        int n0 = __popc(f0);
        if (f0 & (1u << l)) s_blist[__popc(f0 & ((1u << l) - 1u))] = (unsigned char)l;
        if (f1 & (1u << l)) s_blist[n0 + __popc(f1 & ((1u << l) - 1u))] = (unsigned char)(32 + l);
        if (l == 0) s_nact = n0 + __popc(f1);
    }
    if (blockIdx.x < B_) {
        __syncthreads();
        if (!s_act[blockIdx.x]) out[blockIdx.x * O_ + tid] = 0.0f;   // 128 floats
    }
    __syncthreads();
    const int n_items = s_nact * O_ * 2;

    const int gj = tid >> 2, d4 = tid & 3;   // transpose mapping
    const int ihw = w * 4;                   // this warp's 4 i rows (block-local)

    for (int item = blockIdx.x; item < n_items; item += GRID_N) {
        const int ihalf = item & 1;
        const int o     = (item >> 1) & (O_ - 1);
        const int b     = s_blist[item >> 8];

        // ---- stage q (16 rows, duplicated) + k-mask weights ----
        {
            const float2* qg = (const float2*)(q + (size_t)b * LQ * D_
                                               + (size_t)ihalf * 16 * D_);
            #pragma unroll
            for (int t = 0; t < 8; t++) {
                int idx = t * 128 + tid;          // 1024 float2
                float2 v = qg[idx];
                int row = idx >> 6, dp = idx & 63;
                q2[row * D_ + 2 * dp]     = pk2(v.x, v.x);
                q2[row * D_ + 2 * dp + 1] = pk2(v.y, v.y);
            }
            wm[tid]       = mask_at(k_mask, o * LK + tid, mode) ? 0.0f : 1.0f;
            wm[128 + tid] = mask_at(k_mask, o * LK + 128 + tid, mode) ? 0.0f : 1.0f;
        }
        __syncthreads();
        {   // invq: warp w covers rows w*4 .. +4
            #pragma unroll
            for (int r = 0; r < 4; r++) {
                int row = ihw + r;
                float s = 0.0f;
                #pragma unroll
                for (int qd = 0; qd < 4; qd++) {
                    float2 u = upk2(q2[row * D_ + qd * 32 + l]);
                    s += u.x * u.x;
                }
                #pragma unroll
                for (int of = 16; of; of >>= 1) s += __shfl_xor_sync(FULLM, s, of);
                if (l == 0) ivq[row] = 1.0f / fmaxf(sqrtf(s), 1e-12f);
            }
        }

        unsigned long long acc[4][4];
        #pragma unroll
        for (int ii = 0; ii < 4; ii++)
            #pragma unroll
            for (int p = 0; p < 4; p++) acc[ii][p] = 0ull;
        float ksq[8];
        #pragma unroll
        for (int t = 0; t < 8; t++) ksq[t] = 0.0f;

        const float4* kr4 = (const float4*)(k + (size_t)o * LK * D_);

        #pragma unroll 1
        for (int c = 0; c < 8; c++) {        // 8 chunks of 16 d
            __syncthreads();
            // load+transpose: thread handles j = t*32+gj, 4 d at d4*4 (2 MLP-4 groups)
            #pragma unroll
            for (int h = 0; h < 2; h++) {
                float4 v[4];
                #pragma unroll
                for (int t = 0; t < 4; t++)
                    v[t] = kr4[((h * 4 + t) * 32 + gj) * (D_ / 4) + c * 4 + d4];
                #pragma unroll
                for (int t = 0; t < 4; t++) {
                    int j = (h * 4 + t) * 32 + gj;
                    float4 u = v[t];
                    ksq[h * 4 + t] += u.x * u.x + u.y * u.y + u.z * u.z + u.w * u.w;
                    int col = j ^ (d4 << 3);
                    kt[(4 * d4 + 0) * LK + col] = u.x;
                    kt[(4 * d4 + 1) * LK + col] = u.y;
                    kt[(4 * d4 + 2) * LK + col] = u.z;
                    kt[(4 * d4 + 3) * LK + col] = u.w;
                }
            }
            __syncthreads();

            #pragma unroll 4
            for (int d2 = 0; d2 < 8; d2++) {
                const int dl = 2 * d2;
                unsigned long long ka0, ka1, kb0, kb1, ka2, ka3, kb2, kb3;
                {
                    int e0 = (dl >> 2) << 3;
                    const float* r0 = kt + dl * LK;
                    float4 a = *(const float4*)(r0 + ((4 * l) ^ e0));
                    float4 a2 = *(const float4*)(r0 + ((128 + 4 * l) ^ e0));
                    ka0 = pk2(a.x, a.y);  ka1 = pk2(a.z, a.w);
                    ka2 = pk2(a2.x, a2.y); ka3 = pk2(a2.z, a2.w);
                    int e1 = ((dl + 1) >> 2) << 3;
                    const float* r1 = kt + (dl + 1) * LK;
                    float4 b4 = *(const float4*)(r1 + ((4 * l) ^ e1));
                    float4 b2 = *(const float4*)(r1 + ((128 + 4 * l) ^ e1));
                    kb0 = pk2(b4.x, b4.y); kb1 = pk2(b4.z, b4.w);
                    kb2 = pk2(b2.x, b2.y); kb3 = pk2(b2.z, b2.w);
                }
                #pragma unroll
                for (int ii = 0; ii < 4; ii++) {
                    ulonglong2 qq = *(const ulonglong2*)(q2 + (ihw + ii) * D_
                                                         + c * 16 + dl);
                    fma2(acc[ii][0], qq.x, ka0);
                    fma2(acc[ii][1], qq.x, ka1);
                    fma2(acc[ii][2], qq.x, ka2);
                    fma2(acc[ii][3], qq.x, ka3);
                    fma2(acc[ii][0], qq.y, kb0);
                    fma2(acc[ii][1], qq.y, kb1);
                    fma2(acc[ii][2], qq.y, kb2);
                    fma2(acc[ii][3], qq.y, kb3);
                }
            }
        }

        // ---- invk: reduce ksq across d4 (lanes l&3) ----
        #pragma unroll
        for (int t = 0; t < 8; t++) {
            float s = ksq[t];
            s += __shfl_xor_sync(FULLM, s, 1);
            s += __shfl_xor_sync(FULLM, s, 2);
            if (d4 == 0) ivk[t * 32 + gj] = s;
        }
        __syncthreads();
        float s0 = ivk[tid], s1 = ivk[128 + tid];
        __syncthreads();
        ivk[tid]       = 1.0f / fmaxf(sqrtf(s0), 1e-12f);
        ivk[128 + tid] = 1.0f / fmaxf(sqrtf(s1), 1e-12f);
        __syncthreads();

        // ---- epilogue: p_i over lane's 8 j, warp-reduce, log, half-sum ----
        float4 iva = *(const float4*)(ivk + 4 * l);
        float4 ivb = *(const float4*)(ivk + 128 + 4 * l);
        float4 wma = *(const float4*)(wm + 4 * l);
        float4 wmb = *(const float4*)(wm + 128 + 4 * l);
        #pragma unroll
        for (int ii = 0; ii < 4; ii++) {
            float a12 = 12.0f * ivq[ihw + ii];
            float2 f0 = upk2(acc[ii][0]), f1 = upk2(acc[ii][1]);
            float2 f2 = upk2(acc[ii][2]), f3 = upk2(acc[ii][3]);
            float p = wma.x * __expf(a12 * iva.x * f0.x)
                    + wma.y * __expf(a12 * iva.y * f0.y)
                    + wma.z * __expf(a12 * iva.z * f1.x)
                    + wma.w * __expf(a12 * iva.w * f1.y)
                    + wmb.x * __expf(a12 * ivb.x * f2.x)
                    + wmb.y * __expf(a12 * ivb.y * f2.y)
                    + wmb.z * __expf(a12 * ivb.z * f3.x)
                    + wmb.w * __expf(a12 * ivb.w * f3.y);
            #pragma unroll
            for (int of = 16; of; of >>= 1) p += __shfl_xor_sync(FULLM, p, of);
            if (l == 0) red[ihw + ii] = __logf(p);    // -inf if all j masked
        }
        __syncthreads();
        if (tid < 16) {
            float lse = red[tid];
            #pragma unroll
            for (int of = 8; of; of >>= 1)
                lse += __shfl_xor_sync(0xffffu, lse, of);
            if (tid == 0) {
                int idx = b * O_ + o;
                atomicAdd(&g_acc[idx], lse);          // half-partial
                __threadfence();
                int old = atomicAdd(&g_cnt[idx], 1);
                if (old == 1) {                       // second arriver finalizes
                    __threadfence();
                    float tot = *((volatile float*)&g_acc[idx]);
                    float s = tot * (1.0f / 12.0f);
                    s = s / (sqrtf((float)(LQ * LK)) + 1e-6f);
                    s *= fminf(expf(logit_scale[0]), 100.0f);
                    if (!isfinite(s)) s = 0.0f;
                    out[idx] = s;
                    *((volatile float*)&g_acc[idx]) = 0.0f;   // reset for replay
                    *((volatile int*)&g_cnt[idx]) = 0;
                    __threadfence();
                }
            }
        }
        __syncthreads();   // protect smem reuse across items
    }
}

// ---------------------------------------------------------------------------
extern "C" void kernel_launch(void* const* d_in, const int* in_sizes, int n_in,
                              void* d_out, int out_size) {
    const float* q  = (const float*)d_in[0];
    const float* k  = (const float*)d_in[1];
    const void*  qm = d_in[2];
    const void*  km = d_in[3];
    const float* ls = (const float*)d_in[4];
    float* out = (float*)d_out;

    const int smem_bytes =
        (4096 + 16 * LK + LK + LK + 16 + 16) * (int)sizeof(float);  // ~34.9KB
    fused_score_kernel<<<GRID_N, 128, smem_bytes>>>(q, k, qm, km, ls, out);
}

// round 15
// speedup vs baseline: 1.3887x; 1.3887x over previous
#include <cuda_runtime.h>
#include <math.h>
#include <stdint.h>

#define B_  64
#define LQ  32
#define O_  128
#define LK  256
#define D_  128
#define FULLM 0xffffffffu
#define GRID_N 592          // one wave at occupancy 4 on 148 SMs

// smem byte offsets (pitch 40 bf16 per 32-d chunk row)
#define KHI_O   0           // 256*40*2 = 20480
#define KLO_O   20480
#define QHI_O   40960       // 32*40*2 = 2560
#define QLO_O   43520
#define KSQ_O   46080       // 256 f
#define QSQ_O   47104       // 32 f
#define IVK_O   47232       // 256 f
#define IVQ_O   48256       // 32 f
#define WM_O    48384       // 256 f
#define PRED_O  49408       // 128 f
#define SMEM_REQ 50176

__device__ __forceinline__ bool mask_at(const void* buf, int idx, int mode) {
    if (mode == 0) return ((const int*)buf)[idx] != 0;
    if (mode == 2) return ((const float*)buf)[idx] != 0.0f;
    return ((const unsigned char*)buf)[idx] != 0;
}
// pack two f32 -> bf16x2 (lo = first arg in memory order)
__device__ __forceinline__ uint32_t pack_bf(float lo, float hi) {
    uint32_t r;
    asm("cvt.rn.bf16x2.f32 %0, %1, %2;" : "=r"(r) : "f"(hi), "f"(lo));
    return r;
}
__device__ __forceinline__ void mma_bf16(float* d, uint32_t a0, uint32_t a1,
                                         uint32_t a2, uint32_t a3,
                                         uint32_t b0, uint32_t b1) {
    asm volatile(
        "mma.sync.aligned.m16n8k16.row.col.f32.bf16.bf16.f32 "
        "{%0,%1,%2,%3}, {%4,%5,%6,%7}, {%8,%9}, {%0,%1,%2,%3};"
        : "+f"(d[0]), "+f"(d[1]), "+f"(d[2]), "+f"(d[3])
        : "r"(a0), "r"(a1), "r"(a2), "r"(a3), "r"(b0), "r"(b1));
}

// ---------------------------------------------------------------------------
// Grid 592 x 128. Item = (active b, o). D[256 j, 32 i] = kn . qn^T via
// mma.sync m16n8k16 bf16, 3-term split (HiHi + HiLo + LoHi) ~= fp32.
// Warp w owns j in [w*64, w*64+64) (4 m16 tiles) x all 32 i (4 n8 tiles).
// K processed in 4 chunks of 32 d; k/q staged as bf16 hi/lo, pitch 40 bf16.
// ---------------------------------------------------------------------------
__global__ __launch_bounds__(128, 4)
void fused_score_kernel(const float* __restrict__ q,
                        const float* __restrict__ k,
                        const void* __restrict__ q_mask,
                        const void* __restrict__ k_mask,
                        const float* __restrict__ logit_scale,
                        float* __restrict__ out) {
    const int tid = threadIdx.x;
    const int w   = tid >> 5, l = tid & 31;
    const int g   = l >> 2, tg = l & 3;

    __shared__ int s_nact;
    __shared__ unsigned char s_blist[B_];
    __shared__ unsigned char s_act[B_];
    extern __shared__ char sb[];
    float* ksqs = (float*)(sb + KSQ_O);
    float* qsqs = (float*)(sb + QSQ_O);
    float* ivk  = (float*)(sb + IVK_O);
    float* ivq  = (float*)(sb + IVQ_O);
    float* wm   = (float*)(sb + WM_O);
    float* pred = (float*)(sb + PRED_O);

    // ---- Phase A: dtype sniff + active flags + compact list ----
    int mode;
    {
        unsigned word = ((const unsigned*)q_mask)[l];
        unsigned bi = __ballot_sync(FULLM, word <= 1u);
        unsigned bf = __ballot_sync(FULLM, word == 0u || word == 0x3F800000u);
        mode = (bi == FULLM) ? 0 : (bf == FULLM) ? 2 : 1;
    }
    {
        int bb = tid >> 1, sub = tid & 1;
        int any = 0;
        #pragma unroll
        for (int e = 0; e < 16; e++)
            any |= mask_at(q_mask, bb * LQ + sub * 16 + e, mode) ? 1 : 0;
        any |= __shfl_xor_sync(FULLM, any, 1);
        if ((l & 1) == 0) s_act[bb] = (any == 0);
    }
    __syncthreads();
    if (w == 0) {
        unsigned f0 = __ballot_sync(FULLM, s_act[l] != 0);
        unsigned f1 = __ballot_sync(FULLM, s_act[32 + l] != 0);
        int n0 = __popc(f0);
        if (f0 & (1u << l)) s_blist[__popc(f0 & ((1u << l) - 1u))] = (unsigned char)l;
        if (f1 & (1u << l)) s_blist[n0 + __popc(f1 & ((1u << l) - 1u))] = (unsigned char)(32 + l);
        if (l == 0) s_nact = n0 + __popc(f1);
    }
    __syncthreads();
    if (blockIdx.x < B_ && !s_act[blockIdx.x])
        out[blockIdx.x * O_ + tid] = 0.0f;
    const int n_items = s_nact * O_;

    for (int item = blockIdx.x; item < n_items; item += GRID_N) {
        const int b = s_blist[item >> 7];
        const int o = item & (O_ - 1);

        __syncthreads();                    // prev item epilogue done with smem
        ksqs[tid] = 0.0f; ksqs[128 + tid] = 0.0f;
        if (tid < 32) qsqs[tid] = 0.0f;
        wm[tid]       = mask_at(k_mask, o * LK + tid, mode) ? 0.0f : 1.0f;
        wm[128 + tid] = mask_at(k_mask, o * LK + 128 + tid, mode) ? 0.0f : 1.0f;

        float acc[4][4][4];
        #pragma unroll
        for (int mt = 0; mt < 4; mt++)
            #pragma unroll
            for (int nt = 0; nt < 4; nt++)
                #pragma unroll
                for (int e = 0; e < 4; e++) acc[mt][nt][e] = 0.0f;

        const float4* kr4 = (const float4*)(k + (size_t)o * LK * D_);
        const float4* qr4 = (const float4*)(q + (size_t)b * LQ * D_);

        #pragma unroll 1
        for (int c = 0; c < 4; c++) {
            __syncthreads();                 // zeroing visible / prev mma done
            // ---- stage k chunk: rows 256, 32 d (8 float4) ----
            #pragma unroll
            for (int it = 0; it < 16; it++) {
                int idx = it * 128 + tid;
                int row = idx >> 3, f4i = idx & 7;
                float4 v = kr4[row * 32 + c * 8 + f4i];
                float s = v.x*v.x + v.y*v.y + v.z*v.z + v.w*v.w;
                s += __shfl_xor_sync(FULLM, s, 1);
                s += __shfl_xor_sync(FULLM, s, 2);
                s += __shfl_xor_sync(FULLM, s, 4);
                if ((tid & 7) == 0) ksqs[row] += s;
                uint32_t h01 = pack_bf(v.x, v.y), h23 = pack_bf(v.z, v.w);
                float lx = v.x - __uint_as_float(h01 << 16);
                float ly = v.y - __uint_as_float(h01 & 0xFFFF0000u);
                float lz = v.z - __uint_as_float(h23 << 16);
                float lw = v.w - __uint_as_float(h23 & 0xFFFF0000u);
                uint32_t l01 = pack_bf(lx, ly), l23 = pack_bf(lz, lw);
                int byo = row * 80 + f4i * 8;
                *(uint2*)(sb + KHI_O + byo) = make_uint2(h01, h23);
                *(uint2*)(sb + KLO_O + byo) = make_uint2(l01, l23);
            }
            // ---- stage q chunk: 32 rows ----
            #pragma unroll
            for (int it = 0; it < 2; it++) {
                int idx = it * 128 + tid;
                int row = idx >> 3, f4i = idx & 7;
                float4 v = qr4[row * 32 + c * 8 + f4i];
                float s = v.x*v.x + v.y*v.y + v.z*v.z + v.w*v.w;
                s += __shfl_xor_sync(FULLM, s, 1);
                s += __shfl_xor_sync(FULLM, s, 2);
                s += __shfl_xor_sync(FULLM, s, 4);
                if ((tid & 7) == 0) qsqs[row] += s;
                uint32_t h01 = pack_bf(v.x, v.y), h23 = pack_bf(v.z, v.w);
                float lx = v.x - __uint_as_float(h01 << 16);
                float ly = v.y - __uint_as_float(h01 & 0xFFFF0000u);
                float lz = v.z - __uint_as_float(h23 << 16);
                float lw = v.w - __uint_as_float(h23 & 0xFFFF0000u);
                uint32_t l01 = pack_bf(lx, ly), l23 = pack_bf(lz, lw);
                int byo = row * 80 + f4i * 8;
                *(uint2*)(sb + QHI_O + byo) = make_uint2(h01, h23);
                *(uint2*)(sb + QLO_O + byo) = make_uint2(l01, l23);
            }
            __syncthreads();

            // ---- MMA phase: warp w -> j [w*64, +64), all i ----
            #pragma unroll
            for (int kh = 0; kh < 2; kh++) {
                uint32_t bh[4][2], bl[4][2];
                #pragma unroll
                for (int nt = 0; nt < 4; nt++) {
                    int qb = (nt * 8 + g) * 80 + (kh * 16 + 2 * tg) * 2;
                    bh[nt][0] = *(const uint32_t*)(sb + QHI_O + qb);
                    bh[nt][1] = *(const uint32_t*)(sb + QHI_O + qb + 16);
                    bl[nt][0] = *(const uint32_t*)(sb + QLO_O + qb);
                    bl[nt][1] = *(const uint32_t*)(sb + QLO_O + qb + 16);
                }
                #pragma unroll
                for (int mt = 0; mt < 4; mt++) {
                    int r0 = w * 64 + mt * 16 + g;
                    int ab = r0 * 80 + (kh * 16 + 2 * tg) * 2;
                    uint32_t ah0 = *(const uint32_t*)(sb + KHI_O + ab);
                    uint32_t ah1 = *(const uint32_t*)(sb + KHI_O + ab + 8 * 80);
                    uint32_t ah2 = *(const uint32_t*)(sb + KHI_O + ab + 16);
                    uint32_t ah3 = *(const uint32_t*)(sb + KHI_O + ab + 8 * 80 + 16);
                    uint32_t al0 = *(const uint32_t*)(sb + KLO_O + ab);
                    uint32_t al1 = *(const uint32_t*)(sb + KLO_O + ab + 8 * 80);
                    uint32_t al2 = *(const uint32_t*)(sb + KLO_O + ab + 16);
                    uint32_t al3 = *(const uint32_t*)(sb + KLO_O + ab + 8 * 80 + 16);
                    #pragma unroll
                    for (int nt = 0; nt < 4; nt++) {
                        mma_bf16(acc[mt][nt], ah0, ah1, ah2, ah3, bh[nt][0], bh[nt][1]);
                        mma_bf16(acc[mt][nt], ah0, ah1, ah2, ah3, bl[nt][0], bl[nt][1]);
                        mma_bf16(acc[mt][nt], al0, al1, al2, al3, bh[nt][0], bh[nt][1]);
                    }
                }
            }
        }

        // ---- norms ----
        __syncthreads();
        ivk[tid]       = 1.0f / fmaxf(sqrtf(ksqs[tid]), 1e-12f);
        ivk[128 + tid] = 1.0f / fmaxf(sqrtf(ksqs[128 + tid]), 1e-12f);
        if (tid < 32) ivq[tid] = 1.0f / fmaxf(sqrtf(qsqs[tid]), 1e-12f);
        __syncthreads();

        // ---- epilogue: exp-sum over j, reduce, lse ----
        float wj[8], kj[8];
        #pragma unroll
        for (int mt = 0; mt < 4; mt++) {
            int j0 = w * 64 + mt * 16 + g;
            wj[2 * mt]     = wm[j0];       kj[2 * mt]     = 12.0f * ivk[j0];
            wj[2 * mt + 1] = wm[j0 + 8];   kj[2 * mt + 1] = 12.0f * ivk[j0 + 8];
        }
        #pragma unroll
        for (int nt = 0; nt < 4; nt++) {
            int i0 = nt * 8 + 2 * tg;
            float q0 = ivq[i0], q1 = ivq[i0 + 1];
            float s0 = 0.0f, s1 = 0.0f;
            #pragma unroll
            for (int mt = 0; mt < 4; mt++) {
                s0 += wj[2*mt]   * __expf(kj[2*mt]   * q0 * acc[mt][nt][0])
                    + wj[2*mt+1] * __expf(kj[2*mt+1] * q0 * acc[mt][nt][2]);
                s1 += wj[2*mt]   * __expf(kj[2*mt]   * q1 * acc[mt][nt][1])
                    + wj[2*mt+1] * __expf(kj[2*mt+1] * q1 * acc[mt][nt][3]);
            }
            #pragma unroll
            for (int of = 4; of < 32; of <<= 1) {
                s0 += __shfl_xor_sync(FULLM, s0, of);
                s1 += __shfl_xor_sync(FULLM, s1, of);
            }
            if (g == 0) {
                pred[w * 32 + i0]     = s0;
                pred[w * 32 + i0 + 1] = s1;
            }
        }
        __syncthreads();
        if (w == 0) {
            float p = pred[l] + pred[32 + l] + pred[64 + l] + pred[96 + l];
            float lse = __logf(p);                 // -inf if all j masked
            #pragma unroll
            for (int of = 16; of; of >>= 1) lse += __shfl_xor_sync(FULLM, lse, of);
            if (l == 0) {
                float s = lse * (1.0f / 12.0f);
                s = s / (sqrtf((float)(LQ * LK)) + 1e-6f);
                s *= fminf(expf(logit_scale[0]), 100.0f);
                if (!isfinite(s)) s = 0.0f;
                out[b * O_ + o] = s;
            }
        }
    }
}

// ---------------------------------------------------------------------------
extern "C" void kernel_launch(void* const* d_in, const int* in_sizes, int n_in,
                              void* d_out, int out_size) {
    const float* q  = (const float*)d_in[0];
    const float* k  = (const float*)d_in[1];
    const void*  qm = d_in[2];
    const void*  km = d_in[3];
    const float* ls = (const float*)d_in[4];
    float* out = (float*)d_out;

    cudaFuncSetAttribute(fused_score_kernel,
                         cudaFuncAttributeMaxDynamicSharedMemorySize, SMEM_REQ);
    fused_score_kernel<<<GRID_N, 128, SMEM_REQ>>>(q, k, qm, km, ls, out);
}